// round 4
// baseline (speedup 1.0000x reference)
#include <cuda_runtime.h>

#define SS   21      // search size
#define PAD  10
#define BS   4       // block size
#define TILE 24      // BS + SS - 1
#define TP   28      // tile pitch in floats
#define H    256
#define W    256

__global__ __launch_bounds__(96)
void pred_kernel(const float* __restrict__ im1,
                 const float* __restrict__ im2,
                 float* __restrict__ out)
{
    __shared__ __align__(16) float im2t[TILE * TP];
    __shared__ float im1t[16];
    __shared__ float red[16][21];   // per-pixel partial weighted sums over i
    __shared__ float sg[21];        // per-i group min, then per-i weight-sum
    __shared__ float s_min;

    const int t  = threadIdx.x;
    const int bx = blockIdx.x, by = blockIdx.y, b = blockIdx.z;
    const float* i1 = im1 + b * H * W;
    const float* i2 = im2 + b * H * W;

    const int x0 = bx * BS - PAD;
    const int y0 = by * BS - PAD;

    // ---- Phase 0: load 24x24 im2 halo tile ----
    if (bx >= 3 && bx <= 60 && by >= 3 && by <= 60) {
        // interior fast path: no padding, vectorized float2, trivial indexing
        const int chunk = t / 24;          // 0..3
        const int r     = t - chunk * 24;  // 0..23
        const float2* g = (const float2*)(i2 + (y0 + r) * W + x0); // x0 even
        float2* s       = (float2*)&im2t[r * TP];
        s[chunk]     = g[chunk];
        s[chunk + 4] = g[chunk + 4];
        s[chunk + 8] = g[chunk + 8];
    } else {
        // border path: predicated zero-pad
        #pragma unroll
        for (int q = 0; q < 6; q++) {
            int idx = t + q * 96;
            int r = idx / TILE, c = idx - r * TILE;
            int y = y0 + r, x = x0 + c;
            float v = 0.0f;
            if ((unsigned)y < (unsigned)H && (unsigned)x < (unsigned)W)
                v = i2[y * W + x];
            im2t[r * TP + c] = v;
        }
    }
    if (t < 16) {
        int py = t >> 2, px = t & 3;
        im1t[t] = i1[(by * BS + py) * W + bx * BS + px];
    }
    __syncthreads();

    // ---- mapping: t = 4*i + py (py in adjacent lanes) ----
    const int i  = t >> 2;          // shift row 0..20
    const int py = t & 3;           // pixel row 0..3
    const bool act = (t < 84);
    const unsigned gmask = (t >= 64) ? 0x000FFFFFu : 0xFFFFFFFFu;

    float r[TILE];                  // register-resident im2 row (py+i)
    float vol[SS];

    if (act) {
        const float4* rp = (const float4*)&im2t[(py + i) * TP];
        #pragma unroll
        for (int q = 0; q < 6; q++) {
            float4 v = rp[q];
            r[q * 4 + 0] = v.x; r[q * 4 + 1] = v.y;
            r[q * 4 + 2] = v.z; r[q * 4 + 3] = v.w;
        }
        const float a0 = im1t[py * 4 + 0], a1 = im1t[py * 4 + 1];
        const float a2 = im1t[py * 4 + 2], a3 = im1t[py * 4 + 3];

        #pragma unroll
        for (int j = 0; j < SS; j++) {
            vol[j] = fabsf(a0 - r[j])     + fabsf(a1 - r[j + 1])
                   + fabsf(a2 - r[j + 2]) + fabsf(a3 - r[j + 3]);
        }
        // allreduce over py within 4-lane group
        #pragma unroll
        for (int j = 0; j < SS; j++) {
            vol[j] += __shfl_xor_sync(gmask, vol[j], 1);
            vol[j] += __shfl_xor_sync(gmask, vol[j], 2);
        }
        float lmin = vol[0];
        #pragma unroll
        for (int j = 1; j < SS; j++) lmin = fminf(lmin, vol[j]);
        if (py == 0) sg[i] = lmin;
    }
    __syncthreads();

    // ---- second-level min over 21 rows (warp 0) ----
    if (t < 32) {
        float v = (t < SS) ? sg[t] : 1e30f;
        #pragma unroll
        for (int o = 16; o; o >>= 1)
            v = fminf(v, __shfl_xor_sync(0xffffffffu, v, o));
        if (t == 0) s_min = v;
    }
    __syncthreads();

    // ---- Phase 3: fused weights + weighted accumulation ----
    if (act) {
        // w = exp(-6.25*(vol - vmin)) = 2^(K*vol + M), K = -6.25*log2(e)
        const float K = -9.016844005555897f;
        const float M = -K * s_min;
        float lsum = 0.0f;
        float acc0 = 0.f, acc1 = 0.f, acc2 = 0.f, acc3 = 0.f;
        #pragma unroll
        for (int j = 0; j < SS; j++) {
            float e = fmaf(vol[j], K, M);
            float wv;
            asm("ex2.approx.ftz.f32 %0, %1;" : "=f"(wv) : "f"(e));
            lsum += wv;
            acc0 = fmaf(wv, r[j],     acc0);
            acc1 = fmaf(wv, r[j + 1], acc1);
            acc2 = fmaf(wv, r[j + 2], acc2);
            acc3 = fmaf(wv, r[j + 3], acc3);
        }
        if (py == 0) sg[i] = lsum;
        red[py * 4 + 0][i] = acc0;
        red[py * 4 + 1][i] = acc1;
        red[py * 4 + 2][i] = acc2;
        red[py * 4 + 3][i] = acc3;
    }
    __syncthreads();

    // ---- Phase 4: reduce over 21 shift-rows, normalize, store ----
    if (t < 16) {
        float s = 0.0f;
        #pragma unroll
        for (int q = 0; q < SS; q++) s += red[t][q];
        float ws = 0.0f;
        #pragma unroll
        for (int q = 0; q < SS; q++) ws += sg[q];
        int py2 = t >> 2, px2 = t & 3;
        out[b * H * W + (by * BS + py2) * W + bx * BS + px2] = s / ws;
    }
}

extern "C" void kernel_launch(void* const* d_in, const int* in_sizes, int n_in,
                              void* d_out, int out_size) {
    const float* im1 = (const float*)d_in[0];
    const float* im2 = (const float*)d_in[1];
    float* out = (float*)d_out;
    dim3 grid(W / BS, H / BS, 2);   // (64, 64, 2)
    pred_kernel<<<grid, 96>>>(im1, im2, out);
}

// round 5
// speedup vs baseline: 1.1928x; 1.1928x over previous
#include <cuda_runtime.h>

#define SS   21      // search size
#define PAD  10
#define BS   4       // block size
#define TILE 24      // BS + SS - 1
#define TP   28      // tile pitch in floats
#define H    256
#define W    256

__global__ __launch_bounds__(96)
void pred_kernel(const float* __restrict__ im1,
                 const float* __restrict__ im2,
                 float* __restrict__ out)
{
    __shared__ __align__(16) float im2t[TILE * TP];
    __shared__ float im1t[16];
    __shared__ float red[16][21];   // per-pixel partial weighted sums over i
    __shared__ float sg[21];        // per-i group min, then per-i weight-sum
    __shared__ float s_min;

    const int t  = threadIdx.x;
    const int bx = blockIdx.x, by = blockIdx.y, b = blockIdx.z;
    const float* i1 = im1 + b * H * W;
    const float* i2 = im2 + b * H * W;

    const int x0 = bx * BS - PAD;
    const int y0 = by * BS - PAD;

    // ---- Phase 0: load 24x24 im2 halo tile ----
    if (bx >= 3 && bx <= 60 && by >= 3 && by <= 60) {
        // interior fast path: coalesced float2 (x0 even => 8B aligned).
        // t -> (row, c2): warp covers 32 consecutive float2 across ~2.7 rows.
        const int row = t / 12;          // 0..7
        const int c2  = t - row * 12;    // 0..11
        #pragma unroll
        for (int p = 0; p < 3; p++) {
            int r = row + p * 8;
            float2 v = *(const float2*)(i2 + (y0 + r) * W + x0 + c2 * 2);
            *(float2*)&im2t[r * TP + c2 * 2] = v;
        }
    } else {
        // border path: predicated zero-pad, coalesced scalar
        #pragma unroll
        for (int q = 0; q < 6; q++) {
            int idx = t + q * 96;
            int r = idx / TILE, c = idx - r * TILE;
            int y = y0 + r, x = x0 + c;
            float v = 0.0f;
            if ((unsigned)y < (unsigned)H && (unsigned)x < (unsigned)W)
                v = i2[y * W + x];
            im2t[r * TP + c] = v;
        }
    }
    if (t < 16) {
        int py = t >> 2, px = t & 3;
        im1t[t] = i1[(by * BS + py) * W + bx * BS + px];
    }
    __syncthreads();

    // ---- mapping: t = 4*i + py (py in adjacent lanes) ----
    const int i  = t >> 2;          // shift row 0..20
    const int py = t & 3;           // pixel row 0..3
    const bool act = (t < 84);
    const unsigned gmask = (t >= 64) ? 0x000FFFFFu : 0xFFFFFFFFu;

    float r[TILE];                  // register-resident im2 row (py+i)
    float vol[SS];

    if (act) {
        const float4* rp = (const float4*)&im2t[(py + i) * TP];
        #pragma unroll
        for (int q = 0; q < 6; q++) {
            float4 v = rp[q];
            r[q * 4 + 0] = v.x; r[q * 4 + 1] = v.y;
            r[q * 4 + 2] = v.z; r[q * 4 + 3] = v.w;
        }
        const float a0 = im1t[py * 4 + 0], a1 = im1t[py * 4 + 1];
        const float a2 = im1t[py * 4 + 2], a3 = im1t[py * 4 + 3];

        #pragma unroll
        for (int j = 0; j < SS; j++) {
            vol[j] = fabsf(a0 - r[j])     + fabsf(a1 - r[j + 1])
                   + fabsf(a2 - r[j + 2]) + fabsf(a3 - r[j + 3]);
        }
        // allreduce over py within 4-lane group
        #pragma unroll
        for (int j = 0; j < SS; j++) {
            vol[j] += __shfl_xor_sync(gmask, vol[j], 1);
            vol[j] += __shfl_xor_sync(gmask, vol[j], 2);
        }
        float lmin = vol[0];
        #pragma unroll
        for (int j = 1; j < SS; j++) lmin = fminf(lmin, vol[j]);
        if (py == 0) sg[i] = lmin;
    }
    __syncthreads();

    // ---- second-level min over 21 rows (warp 0) ----
    if (t < 32) {
        float v = (t < SS) ? sg[t] : 1e30f;
        #pragma unroll
        for (int o = 16; o; o >>= 1)
            v = fminf(v, __shfl_xor_sync(0xffffffffu, v, o));
        if (t == 0) s_min = v;
    }
    __syncthreads();

    // ---- Phase 3: fused weights + weighted accumulation ----
    if (act) {
        // w = exp(-6.25*(vol - vmin)) = 2^(K*vol + M), K = -6.25*log2(e)
        const float K = -9.016844005555897f;
        const float M = -K * s_min;
        float lsum = 0.0f;
        float acc0 = 0.f, acc1 = 0.f, acc2 = 0.f, acc3 = 0.f;
        #pragma unroll
        for (int j = 0; j < SS; j++) {
            float e = fmaf(vol[j], K, M);
            float wv;
            asm("ex2.approx.ftz.f32 %0, %1;" : "=f"(wv) : "f"(e));
            lsum += wv;
            acc0 = fmaf(wv, r[j],     acc0);
            acc1 = fmaf(wv, r[j + 1], acc1);
            acc2 = fmaf(wv, r[j + 2], acc2);
            acc3 = fmaf(wv, r[j + 3], acc3);
        }
        if (py == 0) sg[i] = lsum;
        red[py * 4 + 0][i] = acc0;
        red[py * 4 + 1][i] = acc1;
        red[py * 4 + 2][i] = acc2;
        red[py * 4 + 3][i] = acc3;
    }
    __syncthreads();

    // ---- Phase 4: reduce over 21 shift-rows, normalize, store ----
    if (t < 16) {
        float s = 0.0f;
        #pragma unroll
        for (int q = 0; q < SS; q++) s += red[t][q];
        float ws = 0.0f;
        #pragma unroll
        for (int q = 0; q < SS; q++) ws += sg[q];
        int py2 = t >> 2, px2 = t & 3;
        out[b * H * W + (by * BS + py2) * W + bx * BS + px2] = s / ws;
    }
}

extern "C" void kernel_launch(void* const* d_in, const int* in_sizes, int n_in,
                              void* d_out, int out_size) {
    const float* im1 = (const float*)d_in[0];
    const float* im2 = (const float*)d_in[1];
    float* out = (float*)d_out;
    dim3 grid(W / BS, H / BS, 2);   // (64, 64, 2)
    pred_kernel<<<grid, 96>>>(im1, im2, out);
}